// round 1
// baseline (speedup 1.0000x reference)
#include <cuda_runtime.h>
#include <cuda_bf16.h>
#include <math.h>

#define BB 2
#define SS 2048
#define DM 1024
#define HH 16
#define DKK 64
#define HDK 1024
#define UU 40
#define SKK 40
#define NR (BB*SS)          // 4096
#define BH (BB*HH)          // 32

// ---------------- device scratch (no allocations allowed) ----------------
__device__ float g_q[(size_t)BH*SS*DKK];      // 16 MB, (b,h,s,d), pre-scaled by 1/sqrt(DK)
__device__ float g_k[(size_t)BH*SS*DKK];      // 16 MB
__device__ float g_v[(size_t)BH*SS*DKK];      // 16 MB
__device__ float g_m[(size_t)BH*SS];          // sparsity measure
__device__ int   g_top[BH*UU];                // selected rows
__device__ float g_vmean[BH*DKK];             // v.mean over s
__device__ float g_delta[BH*UU*DKK];          // upd - vmean
__device__ float g_base[BB*DM];               // (concat_h vmean) @ fc_w
__device__ float g_pre[(size_t)NR*DM];        // pre-layernorm output

// ---------------- 1) QKV GEMM: 128x128 tile, Ktile=16, 256 thr, 8x8/thr ----
__global__ __launch_bounds__(256, 2)
void qkv_gemm(const float* __restrict__ hs,
              const float* __restrict__ wq,
              const float* __restrict__ wk,
              const float* __restrict__ wv)
{
    const int which = blockIdx.z;
    const float* __restrict__ W = (which == 0) ? wq : (which == 1) ? wk : wv;
    float* __restrict__ O = (which == 0) ? g_q : (which == 1) ? g_k : g_v;
    const float scale = (which == 0) ? 0.125f : 1.0f;   // 1/sqrt(64)

    __shared__ float As[16][128];   // [k][m]
    __shared__ float Bs[16][128];   // [k][n]

    const int t   = threadIdx.x;
    const int tx  = t & 15;
    const int ty  = t >> 4;
    const int row0 = blockIdx.y * 128;
    const int n0   = blockIdx.x * 128;

    float acc[8][8];
    #pragma unroll
    for (int i = 0; i < 8; i++)
        #pragma unroll
        for (int j = 0; j < 8; j++) acc[i][j] = 0.f;

    for (int k0 = 0; k0 < DM; k0 += 16) {
        // load A tile (128 x 16), transposed into As[k][m]
        #pragma unroll
        for (int i = 0; i < 2; i++) {
            int idx = t + i * 256;
            int r = idx >> 2;          // 0..127
            int kq = idx & 3;          // 0..3  (float4 along K)
            float4 a = *(const float4*)&hs[(size_t)(row0 + r) * DM + k0 + kq * 4];
            As[kq * 4 + 0][r] = a.x;
            As[kq * 4 + 1][r] = a.y;
            As[kq * 4 + 2][r] = a.z;
            As[kq * 4 + 3][r] = a.w;
        }
        // load B tile (16 x 128)
        #pragma unroll
        for (int i = 0; i < 2; i++) {
            int idx = t + i * 256;
            int kr = idx >> 5;         // 0..15
            int cq = idx & 31;         // 0..31
            *(float4*)&Bs[kr][cq * 4] =
                *(const float4*)&W[(size_t)(k0 + kr) * HDK + n0 + cq * 4];
        }
        __syncthreads();

        #pragma unroll
        for (int kk = 0; kk < 16; kk++) {
            float a[8], b[8];
            *(float4*)&a[0] = *(float4*)&As[kk][ty * 8];
            *(float4*)&a[4] = *(float4*)&As[kk][ty * 8 + 4];
            *(float4*)&b[0] = *(float4*)&Bs[kk][tx * 8];
            *(float4*)&b[4] = *(float4*)&Bs[kk][tx * 8 + 4];
            #pragma unroll
            for (int i = 0; i < 8; i++)
                #pragma unroll
                for (int j = 0; j < 8; j++)
                    acc[i][j] += a[i] * b[j];
        }
        __syncthreads();
    }

    // epilogue: write permuted (b,h,s,d)
    const int c0 = n0 + tx * 8;
    const int h  = c0 >> 6;            // 8-wide j stays in one head
    const int d0 = c0 & 63;
    #pragma unroll
    for (int i = 0; i < 8; i++) {
        int ri = row0 + ty * 8 + i;
        int b  = ri >> 11;             // /S
        int s  = ri & (SS - 1);
        float* dst = &O[(((size_t)(b * HH + h)) * SS + s) * DKK + d0];
        float4 v0 = make_float4(acc[i][0]*scale, acc[i][1]*scale, acc[i][2]*scale, acc[i][3]*scale);
        float4 v1 = make_float4(acc[i][4]*scale, acc[i][5]*scale, acc[i][6]*scale, acc[i][7]*scale);
        *(float4*)&dst[0] = v0;
        *(float4*)&dst[4] = v1;
    }
}

// ---------------- 2) sampled QK scores -> m = max - sum/S ----------------
__global__ void sample_m_kernel(const int* __restrict__ idx)
{
    const int bh   = blockIdx.y;
    const int l    = blockIdx.x * 8 + threadIdx.y;
    const int lane = threadIdx.x;

    const float* __restrict__ qrow = g_q + ((size_t)bh * SS + l) * DKK;
    const float q0 = qrow[lane];
    const float q1 = qrow[lane + 32];
    const float* __restrict__ kbase = g_k + (size_t)bh * SS * DKK;

    float mx = -3.4e38f, sm = 0.f;
    #pragma unroll 4
    for (int j = 0; j < SKK; j++) {
        int kk = idx[l * SKK + j];
        const float* kr = kbase + (size_t)kk * DKK;
        float p = q0 * kr[lane] + q1 * kr[lane + 32];
        #pragma unroll
        for (int o = 16; o > 0; o >>= 1) p += __shfl_xor_sync(0xffffffffu, p, o);
        mx = fmaxf(mx, p);
        sm += p;
    }
    if (lane == 0) g_m[(size_t)bh * SS + l] = mx - sm * (1.0f / (float)SS);
}

// ---------------- 3) top-40 per (b,h), jax tie-break (smaller index) ------
__global__ void topk_kernel()
{
    const int bh = blockIdx.x;
    const int t  = threadIdx.x;     // 256
    __shared__ float sv[SS];
    __shared__ float rv[256];
    __shared__ int   ri[256];

    for (int i = t; i < SS; i += 256) sv[i] = g_m[(size_t)bh * SS + i];
    __syncthreads();

    for (int it = 0; it < UU; it++) {
        float bv = -3.4e38f; int bi = SS;
        for (int i = t; i < SS; i += 256) {
            float v = sv[i];
            if (v > bv) { bv = v; bi = i; }      // ascending i: strict > keeps smallest idx
        }
        rv[t] = bv; ri[t] = bi;
        __syncthreads();
        for (int st = 128; st > 0; st >>= 1) {
            if (t < st) {
                float ov = rv[t + st]; int oi = ri[t + st];
                if (ov > rv[t] || (ov == rv[t] && oi < ri[t])) { rv[t] = ov; ri[t] = oi; }
            }
            __syncthreads();
        }
        if (t == 0) {
            g_top[bh * UU + it] = ri[0];
            sv[ri[0]] = -3.4e38f;
        }
        __syncthreads();
    }
}

// ---------------- 4) v.mean over s per (b,h,d) ----------------------------
__global__ void vmean_kernel()
{
    const int bh = blockIdx.x;
    const int t  = threadIdx.x;     // 256
    const int d  = t & 63, g = t >> 6;
    __shared__ float sh[256];
    float acc = 0.f;
    for (int s = g; s < SS; s += 4)
        acc += g_v[((size_t)bh * SS + s) * DKK + d];
    sh[t] = acc;
    __syncthreads();
    if (t < 64)
        g_vmean[bh * DKK + t] =
            (sh[t] + sh[t + 64] + sh[t + 128] + sh[t + 192]) * (1.0f / (float)SS);
}

// ---------------- 5) attention for selected rows -> delta ----------------
__global__ __launch_bounds__(256)
void attn_kernel()
{
    const int bhu = blockIdx.x;         // b*H*U + h*U + u
    const int bh  = bhu / UU;
    const int t   = threadIdx.x;
    __shared__ float qv[DKK];
    __shared__ float sc[SS];
    __shared__ float red[256];

    const int srow = g_top[bhu];
    if (t < DKK) qv[t] = g_q[((size_t)bh * SS + srow) * DKK + t];
    __syncthreads();

    // scores = q_sel . k_j
    for (int j = t; j < SS; j += 256) {
        const float4* kr = (const float4*)(g_k + ((size_t)bh * SS + j) * DKK);
        float acc = 0.f;
        #pragma unroll
        for (int c = 0; c < 16; c++) {
            float4 kv = kr[c];
            acc += qv[4*c]   * kv.x + qv[4*c+1] * kv.y
                 + qv[4*c+2] * kv.z + qv[4*c+3] * kv.w;
        }
        sc[j] = acc;
    }
    __syncthreads();

    // softmax (max-subtract, accurate expf)
    float mx = -3.4e38f;
    for (int j = t; j < SS; j += 256) mx = fmaxf(mx, sc[j]);
    red[t] = mx; __syncthreads();
    for (int st = 128; st > 0; st >>= 1) {
        if (t < st) red[t] = fmaxf(red[t], red[t + st]);
        __syncthreads();
    }
    mx = red[0];
    __syncthreads();

    float ls = 0.f;
    for (int j = t; j < SS; j += 256) {
        float e = expf(sc[j] - mx);
        sc[j] = e;
        ls += e;
    }
    red[t] = ls; __syncthreads();
    for (int st = 128; st > 0; st >>= 1) {
        if (t < st) red[t] += red[t + st];
        __syncthreads();
    }
    const float inv = 1.0f / red[0];
    __syncthreads();

    // upd_d = inv * sum_j p_j * v[j][d] ; delta = upd - vmean
    const int d = t & 63, g = t >> 6;
    float acc = 0.f;
    const int j0 = g * (SS / 4), j1 = j0 + (SS / 4);
    for (int j = j0; j < j1; j++)
        acc += sc[j] * g_v[((size_t)bh * SS + j) * DKK + d];
    red[t] = acc;
    __syncthreads();
    if (t < 64) {
        float upd = (red[t] + red[t + 64] + red[t + 128] + red[t + 192]) * inv;
        g_delta[bhu * DKK + t] = upd - g_vmean[bh * DKK + t];
    }
}

// ---------------- 6) base row: (concat_h vmean[b]) @ fc_w ----------------
__global__ void base_kernel(const float* __restrict__ fcw)
{
    const int b = blockIdx.y;
    const int n = blockIdx.x * 256 + threadIdx.x;
    __shared__ float cv[DM];
    for (int i = threadIdx.x; i < DM; i += 256) cv[i] = g_vmean[b * DM + i];
    __syncthreads();
    float acc = 0.f;
    #pragma unroll 4
    for (int m = 0; m < DM; m++) acc += cv[m] * fcw[(size_t)m * DM + n];
    g_base[b * DM + n] = acc;
}

// ---------------- 7) pre = residual + base + fc_b ------------------------
__global__ void assemble_kernel(const float* __restrict__ hs,
                                const float* __restrict__ fcb)
{
    size_t i = (size_t)blockIdx.x * 256 + threadIdx.x;     // float4 index
    const size_t total = (size_t)NR * DM / 4;
    if (i >= total) return;
    int row = (int)(i / (DM / 4));
    int c4  = (int)(i % (DM / 4));
    int b   = row >> 11;
    float4 r  = ((const float4*)hs)[i];
    float4 bs = ((const float4*)g_base)[b * (DM / 4) + c4];
    float4 fb = ((const float4*)fcb)[c4];
    float4 o;
    o.x = r.x + bs.x + fb.x;
    o.y = r.y + bs.y + fb.y;
    o.z = r.z + bs.z + fb.z;
    o.w = r.w + bs.w + fb.w;
    ((float4*)g_pre)[i] = o;
}

// ---------------- 8) scatter delta-GEMV into pre -------------------------
__global__ void scatter_kernel(const float* __restrict__ fcw)
{
    const int bhu = blockIdx.x;
    const int bh  = bhu / UU;
    const int h   = bh % HH;
    const int b   = bh / HH;
    const int t   = threadIdx.x;
    __shared__ float dl[DKK];
    const int srow = g_top[bhu];
    if (t < DKK) dl[t] = g_delta[bhu * DKK + t];
    __syncthreads();

    float* dst = g_pre + ((size_t)(b * SS + srow)) * DM;
    const float* w = fcw + (size_t)(h * DKK) * DM;
    for (int n = t; n < DM; n += 256) {
        float acc = 0.f;
        #pragma unroll
        for (int d = 0; d < DKK; d++) acc += dl[d] * w[(size_t)d * DM + n];
        atomicAdd(&dst[n], acc);
    }
}

// ---------------- 9) layernorm -------------------------------------------
__global__ void ln_kernel(const float* __restrict__ lnw,
                          const float* __restrict__ lnb,
                          float* __restrict__ out)
{
    const int row = blockIdx.x;
    const int t   = threadIdx.x;   // 256
    const float* x = g_pre + (size_t)row * DM;
    __shared__ float red[256];

    float s = 0.f;
    for (int i = t; i < DM; i += 256) s += x[i];
    red[t] = s; __syncthreads();
    for (int st = 128; st > 0; st >>= 1) {
        if (t < st) red[t] += red[t + st];
        __syncthreads();
    }
    const float mu = red[0] * (1.0f / (float)DM);
    __syncthreads();

    float v = 0.f;
    for (int i = t; i < DM; i += 256) {
        float dd = x[i] - mu;
        v += dd * dd;
    }
    red[t] = v; __syncthreads();
    for (int st = 128; st > 0; st >>= 1) {
        if (t < st) red[t] += red[t + st];
        __syncthreads();
    }
    const float rstd = rsqrtf(red[0] * (1.0f / (float)DM) + 1e-6f);

    for (int i = t; i < DM; i += 256)
        out[(size_t)row * DM + i] = (x[i] - mu) * rstd * lnw[i] + lnb[i];
}

// ---------------- launch --------------------------------------------------
extern "C" void kernel_launch(void* const* d_in, const int* in_sizes, int n_in,
                              void* d_out, int out_size)
{
    const float* hs  = (const float*)d_in[0];
    const float* wq  = (const float*)d_in[1];
    const float* wk  = (const float*)d_in[2];
    const float* wv  = (const float*)d_in[3];
    const float* fcw = (const float*)d_in[4];
    const float* fcb = (const float*)d_in[5];
    const float* lnw = (const float*)d_in[6];
    const float* lnb = (const float*)d_in[7];
    const int*   idx = (const int*)d_in[8];
    float* out = (float*)d_out;

    dim3 g1(HDK / 128, NR / 128, 3);
    qkv_gemm<<<g1, 256>>>(hs, wq, wk, wv);
    sample_m_kernel<<<dim3(SS / 8, BH), dim3(32, 8)>>>(idx);
    topk_kernel<<<BH, 256>>>();
    vmean_kernel<<<BH, 256>>>();
    attn_kernel<<<BH * UU, 256>>>();
    base_kernel<<<dim3(DM / 256, BB), 256>>>(fcw);
    assemble_kernel<<<(int)(((size_t)NR * DM / 4 + 255) / 256), 256>>>(hs, fcb);
    scatter_kernel<<<BH * UU, 256>>>(fcw);
    ln_kernel<<<NR, 256>>>(lnw, lnb, out);
}

// round 2
// speedup vs baseline: 1.0036x; 1.0036x over previous
#include <cuda_runtime.h>
#include <cuda_bf16.h>
#include <math.h>

#define BB 2
#define SS 2048
#define DM 1024
#define HH 16
#define DKK 64
#define HDK 1024
#define UU 40
#define SKK 40
#define NR (BB*SS)          // 4096
#define BH (BB*HH)          // 32

// ---------------- device scratch (no allocations allowed) ----------------
__device__ float g_q[(size_t)BH*SS*DKK];      // 16 MB, (b,h,s,d), pre-scaled by 1/sqrt(DK)
__device__ float g_k[(size_t)BH*SS*DKK];      // 16 MB
__device__ float g_v[(size_t)BH*SS*DKK];      // 16 MB
__device__ float g_m[(size_t)BH*SS];          // sparsity measure
__device__ int   g_top[BH*UU];                // selected rows
__device__ float g_vmean[BH*DKK];             // v.mean over s
__device__ float g_delta[BH*UU*DKK];          // upd - vmean
__device__ float g_base[BB*DM];               // (concat_h vmean) @ fc_w
__device__ float g_pre[(size_t)NR*DM];        // pre-layernorm output

// ---------------- 1) QKV GEMM: 128x128 tile, Ktile=16, 256 thr, 8x8/thr ----
__global__ __launch_bounds__(256, 2)
void qkv_gemm(const float* __restrict__ hs,
              const float* __restrict__ wq,
              const float* __restrict__ wk,
              const float* __restrict__ wv)
{
    const int which = blockIdx.z;
    const float* __restrict__ W = (which == 0) ? wq : (which == 1) ? wk : wv;
    float* __restrict__ O = (which == 0) ? g_q : (which == 1) ? g_k : g_v;
    const float scale = (which == 0) ? 0.125f : 1.0f;   // 1/sqrt(64)

    __shared__ float As[16][128];   // [k][m]
    __shared__ float Bs[16][128];   // [k][n]

    const int t   = threadIdx.x;
    const int tx  = t & 15;
    const int ty  = t >> 4;
    const int row0 = blockIdx.y * 128;
    const int n0   = blockIdx.x * 128;

    float acc[8][8];
    #pragma unroll
    for (int i = 0; i < 8; i++)
        #pragma unroll
        for (int j = 0; j < 8; j++) acc[i][j] = 0.f;

    for (int k0 = 0; k0 < DM; k0 += 16) {
        // load A tile (128 x 16), transposed into As[k][m]
        #pragma unroll
        for (int i = 0; i < 2; i++) {
            int idx = t + i * 256;
            int r = idx >> 2;          // 0..127
            int kq = idx & 3;          // 0..3  (float4 along K)
            float4 a = *(const float4*)&hs[(size_t)(row0 + r) * DM + k0 + kq * 4];
            As[kq * 4 + 0][r] = a.x;
            As[kq * 4 + 1][r] = a.y;
            As[kq * 4 + 2][r] = a.z;
            As[kq * 4 + 3][r] = a.w;
        }
        // load B tile (16 x 128)
        #pragma unroll
        for (int i = 0; i < 2; i++) {
            int idx = t + i * 256;
            int kr = idx >> 5;         // 0..15
            int cq = idx & 31;         // 0..31
            *(float4*)&Bs[kr][cq * 4] =
                *(const float4*)&W[(size_t)(k0 + kr) * HDK + n0 + cq * 4];
        }
        __syncthreads();

        #pragma unroll
        for (int kk = 0; kk < 16; kk++) {
            float a[8], b[8];
            *(float4*)&a[0] = *(float4*)&As[kk][ty * 8];
            *(float4*)&a[4] = *(float4*)&As[kk][ty * 8 + 4];
            *(float4*)&b[0] = *(float4*)&Bs[kk][tx * 8];
            *(float4*)&b[4] = *(float4*)&Bs[kk][tx * 8 + 4];
            #pragma unroll
            for (int i = 0; i < 8; i++)
                #pragma unroll
                for (int j = 0; j < 8; j++)
                    acc[i][j] += a[i] * b[j];
        }
        __syncthreads();
    }

    // epilogue: write permuted (b,h,s,d)
    const int c0 = n0 + tx * 8;
    const int h  = c0 >> 6;            // 8-wide j stays in one head
    const int d0 = c0 & 63;
    #pragma unroll
    for (int i = 0; i < 8; i++) {
        int ri = row0 + ty * 8 + i;
        int b  = ri >> 11;             // /S
        int s  = ri & (SS - 1);
        float* dst = &O[(((size_t)(b * HH + h)) * SS + s) * DKK + d0];
        float4 v0 = make_float4(acc[i][0]*scale, acc[i][1]*scale, acc[i][2]*scale, acc[i][3]*scale);
        float4 v1 = make_float4(acc[i][4]*scale, acc[i][5]*scale, acc[i][6]*scale, acc[i][7]*scale);
        *(float4*)&dst[0] = v0;
        *(float4*)&dst[4] = v1;
    }
}

// ---------------- 2) sampled QK scores -> m = max - sum/S ----------------
__global__ void sample_m_kernel(const int* __restrict__ idx)
{
    const int bh   = blockIdx.y;
    const int l    = blockIdx.x * 8 + threadIdx.y;
    const int lane = threadIdx.x;

    const float* __restrict__ qrow = g_q + ((size_t)bh * SS + l) * DKK;
    const float q0 = qrow[lane];
    const float q1 = qrow[lane + 32];
    const float* __restrict__ kbase = g_k + (size_t)bh * SS * DKK;

    float mx = -3.4e38f, sm = 0.f;
    #pragma unroll 4
    for (int j = 0; j < SKK; j++) {
        int kk = idx[l * SKK + j];
        const float* kr = kbase + (size_t)kk * DKK;
        float p = q0 * kr[lane] + q1 * kr[lane + 32];
        #pragma unroll
        for (int o = 16; o > 0; o >>= 1) p += __shfl_xor_sync(0xffffffffu, p, o);
        mx = fmaxf(mx, p);
        sm += p;
    }
    if (lane == 0) g_m[(size_t)bh * SS + l] = mx - sm * (1.0f / (float)SS);
}

// ---------------- 3) top-40 per (b,h), jax tie-break (smaller index) ------
__global__ void topk_kernel()
{
    const int bh = blockIdx.x;
    const int t  = threadIdx.x;     // 256
    __shared__ float sv[SS];
    __shared__ float rv[256];
    __shared__ int   ri[256];

    for (int i = t; i < SS; i += 256) sv[i] = g_m[(size_t)bh * SS + i];
    __syncthreads();

    for (int it = 0; it < UU; it++) {
        float bv = -3.4e38f; int bi = SS;
        for (int i = t; i < SS; i += 256) {
            float v = sv[i];
            if (v > bv) { bv = v; bi = i; }      // ascending i: strict > keeps smallest idx
        }
        rv[t] = bv; ri[t] = bi;
        __syncthreads();
        for (int st = 128; st > 0; st >>= 1) {
            if (t < st) {
                float ov = rv[t + st]; int oi = ri[t + st];
                if (ov > rv[t] || (ov == rv[t] && oi < ri[t])) { rv[t] = ov; ri[t] = oi; }
            }
            __syncthreads();
        }
        if (t == 0) {
            g_top[bh * UU + it] = ri[0];
            sv[ri[0]] = -3.4e38f;
        }
        __syncthreads();
    }
}

// ---------------- 4) v.mean over s per (b,h,d) ----------------------------
__global__ void vmean_kernel()
{
    const int bh = blockIdx.x;
    const int t  = threadIdx.x;     // 256
    const int d  = t & 63, g = t >> 6;
    __shared__ float sh[256];
    float acc = 0.f;
    for (int s = g; s < SS; s += 4)
        acc += g_v[((size_t)bh * SS + s) * DKK + d];
    sh[t] = acc;
    __syncthreads();
    if (t < 64)
        g_vmean[bh * DKK + t] =
            (sh[t] + sh[t + 64] + sh[t + 128] + sh[t + 192]) * (1.0f / (float)SS);
}

// ---------------- 5) attention for selected rows -> delta ----------------
__global__ __launch_bounds__(256)
void attn_kernel()
{
    const int bhu = blockIdx.x;         // b*H*U + h*U + u
    const int bh  = bhu / UU;
    const int t   = threadIdx.x;
    __shared__ float qv[DKK];
    __shared__ float sc[SS];
    __shared__ float red[256];

    const int srow = g_top[bhu];
    if (t < DKK) qv[t] = g_q[((size_t)bh * SS + srow) * DKK + t];
    __syncthreads();

    // scores = q_sel . k_j
    for (int j = t; j < SS; j += 256) {
        const float4* kr = (const float4*)(g_k + ((size_t)bh * SS + j) * DKK);
        float acc = 0.f;
        #pragma unroll
        for (int c = 0; c < 16; c++) {
            float4 kv = kr[c];
            acc += qv[4*c]   * kv.x + qv[4*c+1] * kv.y
                 + qv[4*c+2] * kv.z + qv[4*c+3] * kv.w;
        }
        sc[j] = acc;
    }
    __syncthreads();

    // softmax (max-subtract, accurate expf)
    float mx = -3.4e38f;
    for (int j = t; j < SS; j += 256) mx = fmaxf(mx, sc[j]);
    red[t] = mx; __syncthreads();
    for (int st = 128; st > 0; st >>= 1) {
        if (t < st) red[t] = fmaxf(red[t], red[t + st]);
        __syncthreads();
    }
    mx = red[0];
    __syncthreads();

    float ls = 0.f;
    for (int j = t; j < SS; j += 256) {
        float e = expf(sc[j] - mx);
        sc[j] = e;
        ls += e;
    }
    red[t] = ls; __syncthreads();
    for (int st = 128; st > 0; st >>= 1) {
        if (t < st) red[t] += red[t + st];
        __syncthreads();
    }
    const float inv = 1.0f / red[0];
    __syncthreads();

    // upd_d = inv * sum_j p_j * v[j][d] ; delta = upd - vmean
    const int d = t & 63, g = t >> 6;
    float acc = 0.f;
    const int j0 = g * (SS / 4), j1 = j0 + (SS / 4);
    for (int j = j0; j < j1; j++)
        acc += sc[j] * g_v[((size_t)bh * SS + j) * DKK + d];
    red[t] = acc;
    __syncthreads();
    if (t < 64) {
        float upd = (red[t] + red[t + 64] + red[t + 128] + red[t + 192]) * inv;
        g_delta[bhu * DKK + t] = upd - g_vmean[bh * DKK + t];
    }
}

// ---------------- 6) base row: (concat_h vmean[b]) @ fc_w ----------------
__global__ void base_kernel(const float* __restrict__ fcw)
{
    const int b = blockIdx.y;
    const int n = blockIdx.x * 256 + threadIdx.x;
    __shared__ float cv[DM];
    for (int i = threadIdx.x; i < DM; i += 256) cv[i] = g_vmean[b * DM + i];
    __syncthreads();
    float acc = 0.f;
    #pragma unroll 4
    for (int m = 0; m < DM; m++) acc += cv[m] * fcw[(size_t)m * DM + n];
    g_base[b * DM + n] = acc;
}

// ---------------- 7) pre = residual + base + fc_b ------------------------
__global__ void assemble_kernel(const float* __restrict__ hs,
                                const float* __restrict__ fcb)
{
    size_t i = (size_t)blockIdx.x * 256 + threadIdx.x;     // float4 index
    const size_t total = (size_t)NR * DM / 4;
    if (i >= total) return;
    int row = (int)(i / (DM / 4));
    int c4  = (int)(i % (DM / 4));
    int b   = row >> 11;
    float4 r  = ((const float4*)hs)[i];
    float4 bs = ((const float4*)g_base)[b * (DM / 4) + c4];
    float4 fb = ((const float4*)fcb)[c4];
    float4 o;
    o.x = r.x + bs.x + fb.x;
    o.y = r.y + bs.y + fb.y;
    o.z = r.z + bs.z + fb.z;
    o.w = r.w + bs.w + fb.w;
    ((float4*)g_pre)[i] = o;
}

// ---------------- 8) scatter delta-GEMV into pre -------------------------
__global__ void scatter_kernel(const float* __restrict__ fcw)
{
    const int bhu = blockIdx.x;
    const int bh  = bhu / UU;
    const int h   = bh % HH;
    const int b   = bh / HH;
    const int t   = threadIdx.x;
    __shared__ float dl[DKK];
    const int srow = g_top[bhu];
    if (t < DKK) dl[t] = g_delta[bhu * DKK + t];
    __syncthreads();

    float* dst = g_pre + ((size_t)(b * SS + srow)) * DM;
    const float* w = fcw + (size_t)(h * DKK) * DM;
    for (int n = t; n < DM; n += 256) {
        float acc = 0.f;
        #pragma unroll
        for (int d = 0; d < DKK; d++) acc += dl[d] * w[(size_t)d * DM + n];
        atomicAdd(&dst[n], acc);
    }
}

// ---------------- 9) layernorm -------------------------------------------
__global__ void ln_kernel(const float* __restrict__ lnw,
                          const float* __restrict__ lnb,
                          float* __restrict__ out)
{
    const int row = blockIdx.x;
    const int t   = threadIdx.x;   // 256
    const float* x = g_pre + (size_t)row * DM;
    __shared__ float red[256];

    float s = 0.f;
    for (int i = t; i < DM; i += 256) s += x[i];
    red[t] = s; __syncthreads();
    for (int st = 128; st > 0; st >>= 1) {
        if (t < st) red[t] += red[t + st];
        __syncthreads();
    }
    const float mu = red[0] * (1.0f / (float)DM);
    __syncthreads();

    float v = 0.f;
    for (int i = t; i < DM; i += 256) {
        float dd = x[i] - mu;
        v += dd * dd;
    }
    red[t] = v; __syncthreads();
    for (int st = 128; st > 0; st >>= 1) {
        if (t < st) red[t] += red[t + st];
        __syncthreads();
    }
    const float rstd = rsqrtf(red[0] * (1.0f / (float)DM) + 1e-6f);

    for (int i = t; i < DM; i += 256)
        out[(size_t)row * DM + i] = (x[i] - mu) * rstd * lnw[i] + lnb[i];
}

// ---------------- launch --------------------------------------------------
extern "C" void kernel_launch(void* const* d_in, const int* in_sizes, int n_in,
                              void* d_out, int out_size)
{
    const float* hs  = (const float*)d_in[0];
    const float* wq  = (const float*)d_in[1];
    const float* wk  = (const float*)d_in[2];
    const float* wv  = (const float*)d_in[3];
    const float* fcw = (const float*)d_in[4];
    const float* fcb = (const float*)d_in[5];
    const float* lnw = (const float*)d_in[6];
    const float* lnb = (const float*)d_in[7];
    const int*   idx = (const int*)d_in[8];
    float* out = (float*)d_out;

    dim3 g1(HDK / 128, NR / 128, 3);
    qkv_gemm<<<g1, 256>>>(hs, wq, wk, wv);
    sample_m_kernel<<<dim3(SS / 8, BH), dim3(32, 8)>>>(idx);
    topk_kernel<<<BH, 256>>>();
    vmean_kernel<<<BH, 256>>>();
    attn_kernel<<<BH * UU, 256>>>();
    base_kernel<<<dim3(DM / 256, BB), 256>>>(fcw);
    assemble_kernel<<<(int)(((size_t)NR * DM / 4 + 255) / 256), 256>>>(hs, fcb);
    scatter_kernel<<<BH * UU, 256>>>(fcw);
    ln_kernel<<<NR, 256>>>(lnw, lnb, out);
}

// round 4
// speedup vs baseline: 2.2762x; 2.2682x over previous
#include <cuda_runtime.h>
#include <cuda_bf16.h>
#include <math.h>
#include <stdint.h>

#define BB 2
#define SS 2048
#define DM 1024
#define HH 16
#define DKK 64
#define HDK 1024
#define UU 40
#define SKK 40
#define NR (BB*SS)
#define BH (BB*HH)
#define NCH 16

// ---------------- device scratch ----------------
__device__ __align__(256) float g_q[(size_t)BH*SS*DKK];
__device__ __align__(256) float g_k[(size_t)BH*SS*DKK];
__device__ __align__(256) float g_v[(size_t)BH*SS*DKK];
__device__ __align__(256) float g_m[(size_t)BH*SS];
__device__ int   g_top[BH*UU];
__device__ __align__(256) float g_vmean[BH*DKK];
__device__ __align__(256) float g_vpart[BH*8*DKK];
__device__ __align__(256) float g_delta[BH*UU*DKK];
__device__ __align__(256) float g_base[BB*DM];
__device__ __align__(256) float g_pre[(size_t)NR*DM];
__device__ __align__(256) __nv_bfloat16 g_a0[(size_t)NR*DM];
__device__ __align__(256) __nv_bfloat16 g_a1[(size_t)NR*DM];
__device__ __align__(256) __nv_bfloat16 g_b0[(size_t)3*DM*HDK];
__device__ __align__(256) __nv_bfloat16 g_b1[(size_t)3*DM*HDK];
__device__ __align__(256) float g_pmax[BH*NCH*UU];
__device__ __align__(256) float g_psum[BH*NCH*UU];
__device__ __align__(256) float g_po[(size_t)BH*NCH*UU*DKK];

// ---------------- helpers ----------------
__device__ __forceinline__ uint32_t smem_u32(const void* p) {
    uint32_t a;
    asm("{ .reg .u64 t; cvta.to.shared.u64 t, %1; cvt.u32.u64 %0, t; }" : "=r"(a) : "l"(p));
    return a;
}
#define CP16(d, s)   asm volatile("cp.async.cg.shared.global [%0], [%1], 16;" :: "r"(d), "l"(s))
#define CP_COMMIT()  asm volatile("cp.async.commit_group;" ::: "memory")
#define CP_WAIT1()   asm volatile("cp.async.wait_group 1;" ::: "memory")
#define CP_WAIT0()   asm volatile("cp.async.wait_group 0;" ::: "memory")
#define LDSM4(r0,r1,r2,r3,addr) \
    asm volatile("ldmatrix.sync.aligned.m8n8.x4.shared.b16 {%0,%1,%2,%3}, [%4];" \
        : "=r"(r0), "=r"(r1), "=r"(r2), "=r"(r3) : "r"(addr))
#define MMA16816(d0,d1,d2,d3,a0,a1,a2,a3,b0,b1) \
    asm volatile("mma.sync.aligned.m16n8k16.row.col.f32.bf16.bf16.f32 " \
        "{%0,%1,%2,%3}, {%4,%5,%6,%7}, {%8,%9}, {%0,%1,%2,%3};" \
        : "+f"(d0), "+f"(d1), "+f"(d2), "+f"(d3) \
        : "r"(a0), "r"(a1), "r"(a2), "r"(a3), "r"(b0), "r"(b1))

// ---------------- 0a) split hidden_states into 2 bf16 planes -------------
__global__ void split2_hs(const float* __restrict__ hs)
{
    size_t i = (size_t)blockIdx.x * 256 + threadIdx.x;
    float2 x = ((const float2*)hs)[i];
    __nv_bfloat16 h0 = __float2bfloat16(x.x), h1 = __float2bfloat16(x.y);
    __nv_bfloat16 l0 = __float2bfloat16(x.x - __bfloat162float(h0));
    __nv_bfloat16 l1 = __float2bfloat16(x.y - __bfloat162float(h1));
    ((__nv_bfloat162*)g_a0)[i] = __halves2bfloat162(h0, h1);
    ((__nv_bfloat162*)g_a1)[i] = __halves2bfloat162(l0, l1);
}

// ---------------- 0b) transpose W -> [n][k] + 2-split ---------------------
__global__ void wtrans2(const float* __restrict__ wq, const float* __restrict__ wk,
                        const float* __restrict__ wv)
{
    int z = blockIdx.z;
    const float* __restrict__ W = (z == 0) ? wq : (z == 1) ? wk : wv;
    __shared__ float tile[32][33];
    int n0 = blockIdx.x * 32, k0 = blockIdx.y * 32;
    int tx = threadIdx.x, ty = threadIdx.y;
    #pragma unroll
    for (int i = 0; i < 4; i++)
        tile[ty + i*8][tx] = W[(size_t)(k0 + ty + i*8) * HDK + n0 + tx];
    __syncthreads();
    #pragma unroll
    for (int i = 0; i < 4; i++) {
        float x = tile[tx][ty + i*8];
        __nv_bfloat16 h = __float2bfloat16(x);
        __nv_bfloat16 l = __float2bfloat16(x - __bfloat162float(h));
        size_t o = (size_t)z * DM * HDK + (size_t)(n0 + ty + i*8) * DM + k0 + tx;
        g_b0[o] = h; g_b1[o] = l;
    }
}

// ---------------- 1) QKV GEMM via mma.sync bf16 (2-split, 3 products) -----
// CTA tile 128(M) x 256(N), K-chunk 32, 8 warps (2m x 4n), warp tile 64x64.
#define KC 32
#define RSTR 80                       // padded row stride bytes (40 bf16)
#define AP (128*RSTR)                 // 10240 B per A plane
#define BPP (256*RSTR)                // 20480 B per B plane
#define STAGE (2*AP + 2*BPP)          // 61440
#define QSMEM (2*STAGE)               // 122880

static __device__ __forceinline__ void qload(uint32_t st,
    const __nv_bfloat16* __restrict__ A0, const __nv_bfloat16* __restrict__ A1,
    const __nv_bfloat16* __restrict__ B0, const __nv_bfloat16* __restrict__ B1,
    int row0, int n0, int k0, int t)
{
    #pragma unroll
    for (int i = 0; i < 2; i++) {
        int idx = t + i * 256;
        int r = idx >> 2, c = idx & 3;
        uint32_t dst = st + (uint32_t)(r * RSTR + c * 16);
        const char* s0 = (const char*)(A0 + (size_t)(row0 + r) * DM + k0) + c * 16;
        const char* s1 = (const char*)(A1 + (size_t)(row0 + r) * DM + k0) + c * 16;
        CP16(dst, s0);
        CP16(dst + AP, s1);
    }
    #pragma unroll
    for (int i = 0; i < 4; i++) {
        int idx = t + i * 256;
        int r = idx >> 2, c = idx & 3;
        uint32_t dst = st + 2*AP + (uint32_t)(r * RSTR + c * 16);
        const char* s0 = (const char*)(B0 + (size_t)(n0 + r) * DM + k0) + c * 16;
        const char* s1 = (const char*)(B1 + (size_t)(n0 + r) * DM + k0) + c * 16;
        CP16(dst, s0);
        CP16(dst + BPP, s1);
    }
}

__global__ void __launch_bounds__(256, 1) qkv_mma()
{
    extern __shared__ char smem[];
    uint32_t sb = smem_u32(smem);
    const int t = threadIdx.x, warp = t >> 5, lane = t & 31;
    const int which = blockIdx.z;
    const int row0 = blockIdx.y * 128;
    const int n0 = blockIdx.x * 256;
    const __nv_bfloat16* A0 = g_a0;
    const __nv_bfloat16* A1 = g_a1;
    const __nv_bfloat16* B0 = g_b0 + (size_t)which * DM * HDK;
    const __nv_bfloat16* B1 = g_b1 + (size_t)which * DM * HDK;
    const int wm = (warp >> 2) * 64, wn = (warp & 3) * 64;
    const int mi = lane >> 3, r8 = lane & 7;

    float acc[4][8][4];
    #pragma unroll
    for (int i = 0; i < 4; i++)
        #pragma unroll
        for (int j = 0; j < 8; j++) {
            acc[i][j][0] = 0.f; acc[i][j][1] = 0.f; acc[i][j][2] = 0.f; acc[i][j][3] = 0.f;
        }

    qload(sb, A0, A1, B0, B1, row0, n0, 0, t);
    CP_COMMIT();

    for (int c = 0; c < DM / KC; c++) {
        int cur = c & 1;
        if (c + 1 < DM / KC) {
            qload(sb + ((c + 1) & 1) * STAGE, A0, A1, B0, B1, row0, n0, (c + 1) * KC, t);
            CP_COMMIT();
            CP_WAIT1();
        } else CP_WAIT0();
        __syncthreads();

        uint32_t stA = sb + cur * STAGE;
        uint32_t stB = stA + 2 * AP;

        #pragma unroll
        for (int s = 0; s < 2; s++) {
            // fragment addresses for this lane
            // A: 4 m-tiles; x4 matrices: (r, k0-7), (r+8, k0-7), (r, k8-15), (r+8, k8-15)
            uint32_t aoff = (uint32_t)((wm + (mi & 1) * 8 + r8) * RSTR + (s * 16 + (mi >> 1) * 8) * 2);
            // B: x4 covers 2 n-tiles: (n+r, k0-7), (n+r, k8-15), (n+8+r, k0-7), (n+8+r, k8-15)
            uint32_t boff = (uint32_t)((wn + (mi >> 1) * 8 + r8) * RSTR + (s * 16 + (mi & 1) * 8) * 2);

            uint32_t a[4][4], b0f[8][2], b1f[8][2];
            // B plane0 + plane1
            #pragma unroll
            for (int nt2 = 0; nt2 < 4; nt2++) {
                uint32_t ad = stB + boff + nt2 * 16 * RSTR;
                LDSM4(b0f[nt2*2][0], b0f[nt2*2][1], b0f[nt2*2+1][0], b0f[nt2*2+1][1], ad);
                LDSM4(b1f[nt2*2][0], b1f[nt2*2][1], b1f[nt2*2+1][0], b1f[nt2*2+1][1], ad + BPP);
            }
            // A plane0, products A0B0 and A0B1
            #pragma unroll
            for (int mt = 0; mt < 4; mt++) {
                uint32_t ad = stA + aoff + mt * 16 * RSTR;
                LDSM4(a[mt][0], a[mt][1], a[mt][2], a[mt][3], ad);
            }
            #pragma unroll
            for (int mt = 0; mt < 4; mt++)
                #pragma unroll
                for (int nt = 0; nt < 8; nt++) {
                    MMA16816(acc[mt][nt][0], acc[mt][nt][1], acc[mt][nt][2], acc[mt][nt][3],
                             a[mt][0], a[mt][1], a[mt][2], a[mt][3], b0f[nt][0], b0f[nt][1]);
                    MMA16816(acc[mt][nt][0], acc[mt][nt][1], acc[mt][nt][2], acc[mt][nt][3],
                             a[mt][0], a[mt][1], a[mt][2], a[mt][3], b1f[nt][0], b1f[nt][1]);
                }
            // A plane1, product A1B0
            #pragma unroll
            for (int mt = 0; mt < 4; mt++) {
                uint32_t ad = stA + AP + aoff + mt * 16 * RSTR;
                LDSM4(a[mt][0], a[mt][1], a[mt][2], a[mt][3], ad);
            }
            #pragma unroll
            for (int mt = 0; mt < 4; mt++)
                #pragma unroll
                for (int nt = 0; nt < 8; nt++)
                    MMA16816(acc[mt][nt][0], acc[mt][nt][1], acc[mt][nt][2], acc[mt][nt][3],
                             a[mt][0], a[mt][1], a[mt][2], a[mt][3], b0f[nt][0], b0f[nt][1]);
        }
        __syncthreads();
    }

    // epilogue: permuted write (b,h,s,d)
    const float scale = (which == 0) ? 0.125f : 1.0f;
    float* __restrict__ O = (which == 0) ? g_q : (which == 1) ? g_k : g_v;
    const int gid = lane >> 2, tig = lane & 3;
    #pragma unroll
    for (int mt = 0; mt < 4; mt++) {
        int row = row0 + wm + mt * 16 + gid;
        int b = row >> 11, s = row & (SS - 1);
        int b8 = (row + 8) >> 11, s8 = (row + 8) & (SS - 1);
        #pragma unroll
        for (int nt = 0; nt < 8; nt++) {
            int col = n0 + wn + nt * 8 + tig * 2;
            int h = col >> 6, d0c = col & 63;
            float2 v0 = make_float2(acc[mt][nt][0] * scale, acc[mt][nt][1] * scale);
            float2 v1 = make_float2(acc[mt][nt][2] * scale, acc[mt][nt][3] * scale);
            *(float2*)&O[(((size_t)(b  * HH + h)) * SS + s ) * DKK + d0c] = v0;
            *(float2*)&O[(((size_t)(b8 * HH + h)) * SS + s8) * DKK + d0c] = v1;
        }
    }
}

// ---------------- 2) sampled QK scores -> m ------------------------------
__global__ void sample_m_kernel(const int* __restrict__ idx)
{
    const int bh = blockIdx.y;
    const int l = blockIdx.x * 8 + threadIdx.y;
    const int lane = threadIdx.x;
    const float* __restrict__ qrow = g_q + ((size_t)bh * SS + l) * DKK;
    const float q0 = qrow[lane], q1 = qrow[lane + 32];
    const float* __restrict__ kbase = g_k + (size_t)bh * SS * DKK;
    float mx = -3.4e38f, sm = 0.f;
    #pragma unroll 4
    for (int j = 0; j < SKK; j++) {
        int kk = idx[l * SKK + j];
        const float* kr = kbase + (size_t)kk * DKK;
        float p = q0 * kr[lane] + q1 * kr[lane + 32];
        #pragma unroll
        for (int o = 16; o > 0; o >>= 1) p += __shfl_xor_sync(0xffffffffu, p, o);
        mx = fmaxf(mx, p);
        sm += p;
    }
    if (lane == 0) g_m[(size_t)bh * SS + l] = mx - sm * (1.0f / (float)SS);
}

// ---------------- 3) top-40 ----------------------------------------------
__global__ void topk_kernel()
{
    const int bh = blockIdx.x, t = threadIdx.x;
    __shared__ float sv[SS];
    __shared__ float rv[256];
    __shared__ int ri[256];
    for (int i = t; i < SS; i += 256) sv[i] = g_m[(size_t)bh * SS + i];
    __syncthreads();
    for (int it = 0; it < UU; it++) {
        float bv = -3.4e38f; int bi = SS;
        for (int i = t; i < SS; i += 256) {
            float v = sv[i];
            if (v > bv) { bv = v; bi = i; }
        }
        rv[t] = bv; ri[t] = bi;
        __syncthreads();
        for (int st = 128; st > 0; st >>= 1) {
            if (t < st) {
                float ov = rv[t + st]; int oi = ri[t + st];
                if (ov > rv[t] || (ov == rv[t] && oi < ri[t])) { rv[t] = ov; ri[t] = oi; }
            }
            __syncthreads();
        }
        if (t == 0) { g_top[bh * UU + it] = ri[0]; sv[ri[0]] = -3.4e38f; }
        __syncthreads();
    }
}

// ---------------- 4) v mean partials -------------------------------------
__global__ void vmean_part()
{
    const int c = blockIdx.x, bh = blockIdx.y, t = threadIdx.x;
    const int d = t & 63, g = t >> 6;
    __shared__ float sh[256];
    float acc = 0.f;
    for (int s = c * 256 + g; s < c * 256 + 256; s += 4)
        acc += g_v[((size_t)bh * SS + s) * DKK + d];
    sh[t] = acc;
    __syncthreads();
    if (t < 64)
        g_vpart[(bh * 8 + c) * DKK + t] = sh[t] + sh[t+64] + sh[t+128] + sh[t+192];
}

// ---------------- 5) attention partials (flash-style) --------------------
#define JC 128
#define ATTN_SMEM ((2560 + 128*65 + 128*64 + UU*128) * 4)
__global__ void __launch_bounds__(256) attn_part()
{
    const int jc = blockIdx.x, bh = blockIdx.y;
    const int j0 = jc * JC, t = threadIdx.x;
    extern __shared__ float sm[];
    float* qs = sm;                 // 40 x 64
    float* ks = qs + 2560;          // 128 x 65
    float* vs = ks + 128 * 65;      // 128 x 64
    float* sc = vs + 128 * 64;      // 40 x 128

    for (int i = t; i < UU * DKK; i += 256) {
        int u = i >> 6, d = i & 63;
        qs[i] = g_q[((size_t)bh * SS + g_top[bh * UU + u]) * DKK + d];
    }
    for (int i = t; i < JC * DKK; i += 256) {
        int j = i >> 6, d = i & 63;
        ks[j * 65 + d] = g_k[((size_t)bh * SS + j0 + j) * DKK + d];
        vs[i]          = g_v[((size_t)bh * SS + j0 + j) * DKK + d];
    }
    __syncthreads();

    {   // scores
        const int jj = t & 31, ug = t >> 5;
        float acc[5][4];
        #pragma unroll
        for (int a = 0; a < 5; a++) { acc[a][0]=0.f; acc[a][1]=0.f; acc[a][2]=0.f; acc[a][3]=0.f; }
        for (int d = 0; d < DKK; d++) {
            float k0v = ks[jj*65+d], k1v = ks[(jj+32)*65+d];
            float k2v = ks[(jj+64)*65+d], k3v = ks[(jj+96)*65+d];
            #pragma unroll
            for (int a = 0; a < 5; a++) {
                float qv = qs[(ug * 5 + a) * DKK + d];
                acc[a][0] += qv*k0v; acc[a][1] += qv*k1v;
                acc[a][2] += qv*k2v; acc[a][3] += qv*k3v;
            }
        }
        #pragma unroll
        for (int a = 0; a < 5; a++) {
            int u = ug * 5 + a;
            sc[u*JC+jj] = acc[a][0]; sc[u*JC+jj+32] = acc[a][1];
            sc[u*JC+jj+64] = acc[a][2]; sc[u*JC+jj+96] = acc[a][3];
        }
    }
    __syncthreads();

    {   // partial softmax per u
        const int w = t >> 5, lid = t & 31;
        for (int u = w; u < UU; u += 8) {
            float a0 = sc[u*JC+lid], a1 = sc[u*JC+lid+32];
            float a2 = sc[u*JC+lid+64], a3 = sc[u*JC+lid+96];
            float mx = fmaxf(fmaxf(a0, a1), fmaxf(a2, a3));
            #pragma unroll
            for (int o = 16; o > 0; o >>= 1) mx = fmaxf(mx, __shfl_xor_sync(0xffffffffu, mx, o));
            float e0 = expf(a0-mx), e1 = expf(a1-mx), e2 = expf(a2-mx), e3 = expf(a3-mx);
            sc[u*JC+lid] = e0; sc[u*JC+lid+32] = e1; sc[u*JC+lid+64] = e2; sc[u*JC+lid+96] = e3;
            float s = e0 + e1 + e2 + e3;
            #pragma unroll
            for (int o = 16; o > 0; o >>= 1) s += __shfl_xor_sync(0xffffffffu, s, o);
            if (lid == 0) {
                g_pmax[(bh * NCH + jc) * UU + u] = mx;
                g_psum[(bh * NCH + jc) * UU + u] = s;
            }
        }
    }
    __syncthreads();

    {   // o partials
        const int d2 = (t & 31) * 2, g8 = t >> 5;
        float acc[5][2];
        #pragma unroll
        for (int a = 0; a < 5; a++) { acc[a][0] = 0.f; acc[a][1] = 0.f; }
        for (int j = 0; j < JC; j++) {
            float v0 = vs[j*DKK+d2], v1 = vs[j*DKK+d2+1];
            #pragma unroll
            for (int a = 0; a < 5; a++) {
                float p = sc[(g8 * 5 + a) * JC + j];
                acc[a][0] += p * v0; acc[a][1] += p * v1;
            }
        }
        #pragma unroll
        for (int a = 0; a < 5; a++) {
            float* dst = g_po + ((size_t)(bh * NCH + jc) * UU + g8 * 5 + a) * DKK + d2;
            dst[0] = acc[a][0]; dst[1] = acc[a][1];
        }
    }
}

// ---------------- 6) merge partials + vmean finalize -> delta ------------
__global__ void attn_merge()
{
    const int bh = blockIdx.x, t = threadIdx.x;
    if (t < 64) {
        float a = 0.f;
        #pragma unroll
        for (int c = 0; c < 8; c++) a += g_vpart[(bh * 8 + c) * DKK + t];
        g_vmean[bh * DKK + t] = a * (1.0f / (float)SS);
    }
    __syncthreads();
    const int w = t >> 5, lid = t & 31;
    for (int u = w; u < UU; u += 8) {
        float M = -3.4e38f;
        #pragma unroll
        for (int c = 0; c < NCH; c++) M = fmaxf(M, g_pmax[(bh * NCH + c) * UU + u]);
        float wc[NCH], T = 0.f;
        #pragma unroll
        for (int c = 0; c < NCH; c++) {
            wc[c] = expf(g_pmax[(bh * NCH + c) * UU + u] - M);
            T += g_psum[(bh * NCH + c) * UU + u] * wc[c];
        }
        float invT = 1.0f / T;
        for (int dd = lid; dd < DKK; dd += 32) {
            float acc = 0.f;
            #pragma unroll
            for (int c = 0; c < NCH; c++)
                acc += wc[c] * g_po[((size_t)(bh * NCH + c) * UU + u) * DKK + dd];
            g_delta[(bh * UU + u) * DKK + dd] = acc * invT - g_vmean[bh * DKK + dd];
        }
    }
}

// ---------------- 7) base row --------------------------------------------
__global__ void base_kernel(const float* __restrict__ fcw)
{
    const int b = blockIdx.y;
    const int n0 = blockIdx.x * 64;
    const int t = threadIdx.x;
    const int nl = t & 63, mg = t >> 6;
    __shared__ float cv[DM];
    __shared__ float part[4][64];
    for (int i = t; i < DM; i += 256) cv[i] = g_vmean[b * DM + i];
    __syncthreads();
    float acc = 0.f;
    for (int m = mg * 256; m < mg * 256 + 256; m++)
        acc += cv[m] * fcw[(size_t)m * DM + n0 + nl];
    part[mg][nl] = acc;
    __syncthreads();
    if (t < 64)
        g_base[b * DM + n0 + t] = part[0][t] + part[1][t] + part[2][t] + part[3][t];
}

// ---------------- 8) pre = residual + base + fc_b ------------------------
__global__ void assemble_kernel(const float* __restrict__ hs, const float* __restrict__ fcb)
{
    size_t i = (size_t)blockIdx.x * 256 + threadIdx.x;
    int row = (int)(i / (DM / 4));
    int c4 = (int)(i % (DM / 4));
    int b = row >> 11;
    float4 r = ((const float4*)hs)[i];
    float4 bs = ((const float4*)g_base)[b * (DM / 4) + c4];
    float4 fb = ((const float4*)fcb)[c4];
    float4 o;
    o.x = r.x + bs.x + fb.x; o.y = r.y + bs.y + fb.y;
    o.z = r.z + bs.z + fb.z; o.w = r.w + bs.w + fb.w;
    ((float4*)g_pre)[i] = o;
}

// ---------------- 9) scatter delta-GEMM (grouped per bh) -----------------
__global__ void __launch_bounds__(256) scatter_kernel(const float* __restrict__ fcw)
{
    const int bh = blockIdx.y;
    const int n0 = blockIdx.x * 256;
    const int h = bh % HH, b = bh / HH;
    const int t = threadIdx.x;
    __shared__ float dl[UU * DKK];
    __shared__ int rows[UU];
    for (int i = t; i < UU * DKK; i += 256) dl[i] = g_delta[bh * UU * DKK + i];
    if (t < UU) rows[t] = g_top[bh * UU + t];
    __syncthreads();

    const int n = n0 + t;
    float acc[UU];
    #pragma unroll
    for (int u = 0; u < UU; u++) acc[u] = 0.f;
    const float* w = fcw + (size_t)(h * DKK) * DM + n;
    for (int d = 0; d < DKK; d++) {
        float wv = w[(size_t)d * DM];
        #pragma unroll
        for (int u = 0; u < UU; u++) acc[u] += dl[u * DKK + d] * wv;
    }
    #pragma unroll
    for (int u = 0; u < UU; u++)
        atomicAdd(&g_pre[((size_t)(b * SS + rows[u])) * DM + n], acc[u]);
}

// ---------------- 10) layernorm ------------------------------------------
__global__ void ln_kernel(const float* __restrict__ lnw, const float* __restrict__ lnb,
                          float* __restrict__ out)
{
    const int row = blockIdx.x, t = threadIdx.x;
    const float* x = g_pre + (size_t)row * DM;
    __shared__ float red[256];
    float s = 0.f;
    for (int i = t; i < DM; i += 256) s += x[i];
    red[t] = s; __syncthreads();
    for (int st = 128; st > 0; st >>= 1) { if (t < st) red[t] += red[t + st]; __syncthreads(); }
    const float mu = red[0] * (1.0f / (float)DM);
    __syncthreads();
    float v = 0.f;
    for (int i = t; i < DM; i += 256) { float dd = x[i] - mu; v += dd * dd; }
    red[t] = v; __syncthreads();
    for (int st = 128; st > 0; st >>= 1) { if (t < st) red[t] += red[t + st]; __syncthreads(); }
    const float rstd = rsqrtf(red[0] * (1.0f / (float)DM) + 1e-6f);
    for (int i = t; i < DM; i += 256)
        out[(size_t)row * DM + i] = (x[i] - mu) * rstd * lnw[i] + lnb[i];
}

// ---------------- launch --------------------------------------------------
extern "C" void kernel_launch(void* const* d_in, const int* in_sizes, int n_in,
                              void* d_out, int out_size)
{
    const float* hs  = (const float*)d_in[0];
    const float* wq  = (const float*)d_in[1];
    const float* wk  = (const float*)d_in[2];
    const float* wv  = (const float*)d_in[3];
    const float* fcw = (const float*)d_in[4];
    const float* fcb = (const float*)d_in[5];
    const float* lnw = (const float*)d_in[6];
    const float* lnb = (const float*)d_in[7];
    const int*   idx = (const int*)d_in[8];
    float* out = (float*)d_out;

    cudaFuncSetAttribute(qkv_mma, cudaFuncAttributeMaxDynamicSharedMemorySize, QSMEM);
    cudaFuncSetAttribute(attn_part, cudaFuncAttributeMaxDynamicSharedMemorySize, ATTN_SMEM);

    split2_hs<<<(int)((size_t)NR * DM / 2 / 256), 256>>>(hs);
    wtrans2<<<dim3(HDK / 32, DM / 32, 3), dim3(32, 8)>>>(wq, wk, wv);
    qkv_mma<<<dim3(HDK / 256, NR / 128, 3), 256, QSMEM>>>();
    sample_m_kernel<<<dim3(SS / 8, BH), dim3(32, 8)>>>(idx);
    topk_kernel<<<BH, 256>>>();
    vmean_part<<<dim3(8, BH), 256>>>();
    attn_part<<<dim3(NCH, BH), 256, ATTN_SMEM>>>();
    attn_merge<<<BH, 256>>>();
    base_kernel<<<dim3(DM / 64, BB), 256>>>(fcw);
    assemble_kernel<<<(int)((size_t)NR * DM / 4 / 256), 256>>>(hs, fcb);
    scatter_kernel<<<dim3(DM / 256, BH), 256>>>(fcw);
    ln_kernel<<<NR, 256>>>(lnw, lnb, out);
}

// round 5
// speedup vs baseline: 2.6659x; 1.1712x over previous
#include <cuda_runtime.h>
#include <cuda_bf16.h>
#include <math.h>
#include <stdint.h>

#define BB 2
#define SS 2048
#define DM 1024
#define HH 16
#define DKK 64
#define HDK 1024
#define UU 40
#define SKK 40
#define NR (BB*SS)
#define BH (BB*HH)
#define NCH 16

// ---------------- device scratch ----------------
__device__ __align__(256) float g_q[(size_t)BH*SS*DKK];
__device__ __align__(256) float g_k[(size_t)BH*SS*DKK];
__device__ __align__(256) float g_v[(size_t)BH*SS*DKK];
__device__ __align__(256) float g_m[(size_t)BH*SS];
__device__ int   g_top[BH*UU];
__device__ __align__(256) float g_vmean[BH*DKK];
__device__ __align__(256) float g_vpart[BH*8*DKK];
__device__ __align__(256) float g_delta[BH*UU*DKK];
__device__ __align__(256) float g_base[BB*DM];
__device__ __align__(256) float g_pre[(size_t)NR*DM];
// packed bf16 planes for bulk-copy GEMM
// A: [rowblk 32][kchunk 32][128 rows x 80B]   (10240 B / block)
// B: [which 3][nblk 4][kchunk 32][256 rows x 80B] (20480 B / block)
__device__ __align__(256) char g_pa0[10485760];
__device__ __align__(256) char g_pa1[10485760];
__device__ __align__(256) char g_pb0[7864320];
__device__ __align__(256) char g_pb1[7864320];
__device__ __align__(256) float g_pmax[BH*NCH*UU];
__device__ __align__(256) float g_psum[BH*NCH*UU];
__device__ __align__(256) float g_po[(size_t)BH*NCH*UU*DKK];

// ---------------- helpers ----------------
__device__ __forceinline__ uint32_t smem_u32(const void* p) {
    uint32_t a;
    asm("{ .reg .u64 t; cvta.to.shared.u64 t, %1; cvt.u32.u64 %0, t; }" : "=r"(a) : "l"(p));
    return a;
}
#define MB_INIT(mb, c)   asm volatile("mbarrier.init.shared.b64 [%0], %1;" :: "r"((uint32_t)(mb)), "r"((uint32_t)(c)) : "memory")
#define MB_EXPECT(mb, bytes) asm volatile("mbarrier.arrive.expect_tx.shared.b64 _, [%0], %1;" :: "r"((uint32_t)(mb)), "r"((uint32_t)(bytes)) : "memory")
#define MB_WAIT(mb, pa) do { \
    uint32_t _m = (uint32_t)(mb), _p = (uint32_t)(pa), _d; \
    asm volatile("{ .reg .pred p; mbarrier.try_wait.parity.acquire.cta.shared::cta.b64 p, [%1], %2; selp.b32 %0, 1, 0, p; }" : "=r"(_d) : "r"(_m), "r"(_p) : "memory"); \
    if (!_d) { asm volatile("{ .reg .pred P1;\nWL_%=: mbarrier.try_wait.parity.acquire.cta.shared::cta.b64 P1, [%0], %1, 0x989680;\n @P1 bra.uni WD_%=;\n bra.uni WL_%=;\nWD_%=: }" :: "r"(_m), "r"(_p) : "memory"); } } while (0)
#define BULK_G2S(dst, src, bytes, mb) \
    asm volatile("cp.async.bulk.shared::cluster.global.mbarrier::complete_tx::bytes [%0], [%1], %2, [%3];" \
        :: "r"((uint32_t)(dst)), "l"(src), "r"((uint32_t)(bytes)), "r"((uint32_t)(mb)) : "memory")
#define LDSM4(r0,r1,r2,r3,addr) \
    asm volatile("ldmatrix.sync.aligned.m8n8.x4.shared.b16 {%0,%1,%2,%3}, [%4];" \
        : "=r"(r0), "=r"(r1), "=r"(r2), "=r"(r3) : "r"(addr))
#define MMA16816(d0,d1,d2,d3,a0,a1,a2,a3,b0,b1) \
    asm volatile("mma.sync.aligned.m16n8k16.row.col.f32.bf16.bf16.f32 " \
        "{%0,%1,%2,%3}, {%4,%5,%6,%7}, {%8,%9}, {%0,%1,%2,%3};" \
        : "+f"(d0), "+f"(d1), "+f"(d2), "+f"(d3) \
        : "r"(a0), "r"(a1), "r"(a2), "r"(a3), "r"(b0), "r"(b1))

#define RSTR 80
#define AP 10240
#define BPP 20480
#define STG 61440
#define NSTG 3
#define QSMEM (NSTG*STG)
#define NCHK 32

// ---------------- 0a) split hidden_states -> packed 2-plane bf16 ---------
__global__ void split2_hs(const float* __restrict__ hs)
{
    size_t i = (size_t)blockIdx.x * 256 + threadIdx.x;   // pair index
    int row = (int)(i >> 9);
    int k = (int)(i & 511) * 2;
    float2 x = ((const float2*)hs)[i];
    __nv_bfloat16 h0 = __float2bfloat16(x.x), h1 = __float2bfloat16(x.y);
    __nv_bfloat16 l0 = __float2bfloat16(x.x - __bfloat162float(h0));
    __nv_bfloat16 l1 = __float2bfloat16(x.y - __bfloat162float(h1));
    size_t off = ((size_t)((row >> 7) * 32 + (k >> 5))) * AP + (row & 127) * RSTR + (k & 31) * 2;
    *(__nv_bfloat162*)(g_pa0 + off) = __halves2bfloat162(h0, h1);
    *(__nv_bfloat162*)(g_pa1 + off) = __halves2bfloat162(l0, l1);
}

// ---------------- 0b) transpose W -> packed [n][k] 2-plane ----------------
__global__ void wtrans2(const float* __restrict__ wq, const float* __restrict__ wk,
                        const float* __restrict__ wv)
{
    int z = blockIdx.z;
    const float* __restrict__ W = (z == 0) ? wq : (z == 1) ? wk : wv;
    const float wsc = (z == 0) ? 0.125f : 1.0f;   // fold 1/sqrt(DK) into wq
    __shared__ float tile[32][33];
    int n0 = blockIdx.x * 32, k0 = blockIdx.y * 32;
    int tx = threadIdx.x, ty = threadIdx.y;
    #pragma unroll
    for (int i = 0; i < 4; i++)
        tile[ty + i*8][tx] = W[(size_t)(k0 + ty + i*8) * HDK + n0 + tx] * wsc;
    __syncthreads();
    #pragma unroll
    for (int i = 0; i < 4; i++) {
        float x = tile[tx][ty + i*8];
        __nv_bfloat16 h = __float2bfloat16(x);
        __nv_bfloat16 l = __float2bfloat16(x - __bfloat162float(h));
        int n = n0 + ty + i*8, k = k0 + tx;
        size_t off = (((size_t)(z * 4) + (n >> 8)) * 32 + (k >> 5)) * BPP + (n & 255) * RSTR + (k & 31) * 2;
        *(__nv_bfloat16*)(g_pb0 + off) = h;
        *(__nv_bfloat16*)(g_pb1 + off) = l;
    }
}

// ---------------- 1) QKV GEMM: mma.sync + cp.async.bulk pipeline ---------
__global__ void __launch_bounds__(256, 1) qkv_mma()
{
    extern __shared__ char smem[];
    __shared__ uint64_t mbars[NSTG];
    uint32_t sb = smem_u32(smem);
    const int t = threadIdx.x, warp = t >> 5, lane = t & 31;
    const int which = blockIdx.z;
    const int rb = blockIdx.y;           // row block (128 rows)
    const int nb = blockIdx.x;           // n block (256 cols)
    const int row0 = rb * 128, n0 = nb * 256;
    const int wm = (warp >> 2) * 64, wn = (warp & 3) * 64;
    const int mi = lane >> 3, r8 = lane & 7;

    uint32_t mb0 = smem_u32(&mbars[0]);
    if (t == 0) {
        #pragma unroll
        for (int i = 0; i < NSTG; i++) MB_INIT(mb0 + i * 8, 1);
    }
    __syncthreads();

    const char* sA0 = g_pa0 + (size_t)rb * 32 * AP;
    const char* sA1 = g_pa1 + (size_t)rb * 32 * AP;
    const char* sB0 = g_pb0 + (size_t)(which * 4 + nb) * 32 * BPP;
    const char* sB1 = g_pb1 + (size_t)(which * 4 + nb) * 32 * BPP;

    if (t == 0) {
        #pragma unroll
        for (int c = 0; c < NSTG; c++) {
            uint32_t mb = mb0 + c * 8;
            uint32_t dst = sb + c * STG;
            MB_EXPECT(mb, STG);
            BULK_G2S(dst,              sA0 + (size_t)c * AP, AP, mb);
            BULK_G2S(dst + AP,         sA1 + (size_t)c * AP, AP, mb);
            BULK_G2S(dst + 2*AP,       sB0 + (size_t)c * BPP, BPP, mb);
            BULK_G2S(dst + 2*AP + BPP, sB1 + (size_t)c * BPP, BPP, mb);
        }
    }

    float acc[4][8][4];
    #pragma unroll
    for (int i = 0; i < 4; i++)
        #pragma unroll
        for (int j = 0; j < 8; j++) {
            acc[i][j][0] = 0.f; acc[i][j][1] = 0.f; acc[i][j][2] = 0.f; acc[i][j][3] = 0.f;
        }

    for (int c = 0; c < NCHK; c++) {
        int s = c % NSTG;
        MB_WAIT(mb0 + s * 8, (c / NSTG) & 1);

        uint32_t stA = sb + s * STG;
        uint32_t stB = stA + 2 * AP;

        #pragma unroll
        for (int si = 0; si < 2; si++) {
            uint32_t aoff = (uint32_t)((wm + (mi & 1) * 8 + r8) * RSTR + (si * 16 + (mi >> 1) * 8) * 2);
            uint32_t boff = (uint32_t)((wn + (mi >> 1) * 8 + r8) * RSTR + (si * 16 + (mi & 1) * 8) * 2);

            uint32_t a[4][4], b0f[8][2], b1f[8][2];
            #pragma unroll
            for (int nt2 = 0; nt2 < 4; nt2++) {
                uint32_t ad = stB + boff + nt2 * 16 * RSTR;
                LDSM4(b0f[nt2*2][0], b0f[nt2*2][1], b0f[nt2*2+1][0], b0f[nt2*2+1][1], ad);
                LDSM4(b1f[nt2*2][0], b1f[nt2*2][1], b1f[nt2*2+1][0], b1f[nt2*2+1][1], ad + BPP);
            }
            #pragma unroll
            for (int mt = 0; mt < 4; mt++) {
                uint32_t ad = stA + aoff + mt * 16 * RSTR;
                LDSM4(a[mt][0], a[mt][1], a[mt][2], a[mt][3], ad);
            }
            #pragma unroll
            for (int mt = 0; mt < 4; mt++)
                #pragma unroll
                for (int nt = 0; nt < 8; nt++) {
                    MMA16816(acc[mt][nt][0], acc[mt][nt][1], acc[mt][nt][2], acc[mt][nt][3],
                             a[mt][0], a[mt][1], a[mt][2], a[mt][3], b0f[nt][0], b0f[nt][1]);
                    MMA16816(acc[mt][nt][0], acc[mt][nt][1], acc[mt][nt][2], acc[mt][nt][3],
                             a[mt][0], a[mt][1], a[mt][2], a[mt][3], b1f[nt][0], b1f[nt][1]);
                }
            #pragma unroll
            for (int mt = 0; mt < 4; mt++) {
                uint32_t ad = stA + AP + aoff + mt * 16 * RSTR;
                LDSM4(a[mt][0], a[mt][1], a[mt][2], a[mt][3], ad);
            }
            #pragma unroll
            for (int mt = 0; mt < 4; mt++)
                #pragma unroll
                for (int nt = 0; nt < 8; nt++)
                    MMA16816(acc[mt][nt][0], acc[mt][nt][1], acc[mt][nt][2], acc[mt][nt][3],
                             a[mt][0], a[mt][1], a[mt][2], a[mt][3], b0f[nt][0], b0f[nt][1]);
        }
        __syncthreads();
        if (t == 0 && c + NSTG < NCHK) {
            int cn = c + NSTG;
            uint32_t mb = mb0 + s * 8;
            uint32_t dst = sb + s * STG;
            MB_EXPECT(mb, STG);
            BULK_G2S(dst,              sA0 + (size_t)cn * AP, AP, mb);
            BULK_G2S(dst + AP,         sA1 + (size_t)cn * AP, AP, mb);
            BULK_G2S(dst + 2*AP,       sB0 + (size_t)cn * BPP, BPP, mb);
            BULK_G2S(dst + 2*AP + BPP, sB1 + (size_t)cn * BPP, BPP, mb);
        }
    }

    // epilogue: permuted write (b,h,s,d); scale folded into wq
    float* __restrict__ O = (which == 0) ? g_q : (which == 1) ? g_k : g_v;
    const int gid = lane >> 2, tig = lane & 3;
    #pragma unroll
    for (int mt = 0; mt < 4; mt++) {
        int row = row0 + wm + mt * 16 + gid;
        int b = row >> 11, s = row & (SS - 1);
        int b8 = (row + 8) >> 11, s8 = (row + 8) & (SS - 1);
        #pragma unroll
        for (int nt = 0; nt < 8; nt++) {
            int col = n0 + wn + nt * 8 + tig * 2;
            int h = col >> 6, d0c = col & 63;
            float2 v0 = make_float2(acc[mt][nt][0], acc[mt][nt][1]);
            float2 v1 = make_float2(acc[mt][nt][2], acc[mt][nt][3]);
            *(float2*)&O[(((size_t)(b  * HH + h)) * SS + s ) * DKK + d0c] = v0;
            *(float2*)&O[(((size_t)(b8 * HH + h)) * SS + s8) * DKK + d0c] = v1;
        }
    }
}

// ---------------- 2) sampled QK scores -> m (8-way MLP) ------------------
__global__ void sample_m_kernel(const int* __restrict__ idx)
{
    const int bh = blockIdx.y;
    const int warp = threadIdx.x >> 5, lane = threadIdx.x & 31;
    const int l = blockIdx.x * 8 + warp;
    const int jg = lane >> 2, dl = lane & 3;
    const float4* qr = (const float4*)(g_q + ((size_t)bh * SS + l) * DKK) + dl * 4;
    float4 q0 = qr[0], q1 = qr[1], q2 = qr[2], q3 = qr[3];
    const float* __restrict__ kbase = g_k + (size_t)bh * SS * DKK;
    const int* __restrict__ ip = idx + l * SKK;
    float mx = -3.4e38f, sm = 0.f;
    #pragma unroll
    for (int jt = 0; jt < SKK; jt += 8) {
        int kk = ip[jt + jg];
        const float4* kr = (const float4*)(kbase + (size_t)kk * DKK) + dl * 4;
        float4 k0 = kr[0], k1 = kr[1], k2 = kr[2], k3 = kr[3];
        float acc = q0.x*k0.x + q0.y*k0.y + q0.z*k0.z + q0.w*k0.w
                  + q1.x*k1.x + q1.y*k1.y + q1.z*k1.z + q1.w*k1.w
                  + q2.x*k2.x + q2.y*k2.y + q2.z*k2.z + q2.w*k2.w
                  + q3.x*k3.x + q3.y*k3.y + q3.z*k3.z + q3.w*k3.w;
        acc += __shfl_xor_sync(0xffffffffu, acc, 1);
        acc += __shfl_xor_sync(0xffffffffu, acc, 2);
        mx = fmaxf(mx, acc);
        sm += acc;
    }
    #pragma unroll
    for (int o = 4; o < 32; o <<= 1) {
        mx = fmaxf(mx, __shfl_xor_sync(0xffffffffu, mx, o));
        sm += __shfl_xor_sync(0xffffffffu, sm, o);
    }
    if (lane == 0) g_m[(size_t)bh * SS + l] = mx - sm * (1.0f / (float)SS);
}

// ---------------- 3) top-40 ----------------------------------------------
__global__ void topk_kernel()
{
    const int bh = blockIdx.x, t = threadIdx.x;
    __shared__ float sv[SS];
    __shared__ float rv[256];
    __shared__ int ri[256];
    for (int i = t; i < SS; i += 256) sv[i] = g_m[(size_t)bh * SS + i];
    __syncthreads();
    for (int it = 0; it < UU; it++) {
        float bv = -3.4e38f; int bi = SS;
        for (int i = t; i < SS; i += 256) {
            float v = sv[i];
            if (v > bv) { bv = v; bi = i; }
        }
        rv[t] = bv; ri[t] = bi;
        __syncthreads();
        for (int st = 128; st > 0; st >>= 1) {
            if (t < st) {
                float ov = rv[t + st]; int oi = ri[t + st];
                if (ov > rv[t] || (ov == rv[t] && oi < ri[t])) { rv[t] = ov; ri[t] = oi; }
            }
            __syncthreads();
        }
        if (t == 0) { g_top[bh * UU + it] = ri[0]; sv[ri[0]] = -3.4e38f; }
        __syncthreads();
    }
}

// ---------------- 4) v mean partials -------------------------------------
__global__ void vmean_part()
{
    const int c = blockIdx.x, bh = blockIdx.y, t = threadIdx.x;
    const int d = t & 63, g = t >> 6;
    __shared__ float sh[256];
    float acc = 0.f;
    for (int s = c * 256 + g; s < c * 256 + 256; s += 4)
        acc += g_v[((size_t)bh * SS + s) * DKK + d];
    sh[t] = acc;
    __syncthreads();
    if (t < 64)
        g_vpart[(bh * 8 + c) * DKK + t] = sh[t] + sh[t+64] + sh[t+128] + sh[t+192];
}

// ---------------- 5) attention partials (flash-style) --------------------
#define JC 128
#define ATTN_SMEM ((2560 + 128*65 + 128*64 + UU*128) * 4)
__global__ void __launch_bounds__(256) attn_part()
{
    const int jc = blockIdx.x, bh = blockIdx.y;
    const int j0 = jc * JC, t = threadIdx.x;
    extern __shared__ float sm[];
    float* qs = sm;
    float* ks = qs + 2560;
    float* vs = ks + 128 * 65;
    float* sc = vs + 128 * 64;

    for (int i = t; i < UU * DKK; i += 256) {
        int u = i >> 6, d = i & 63;
        qs[i] = g_q[((size_t)bh * SS + g_top[bh * UU + u]) * DKK + d];
    }
    for (int i = t; i < JC * DKK; i += 256) {
        int j = i >> 6, d = i & 63;
        ks[j * 65 + d] = g_k[((size_t)bh * SS + j0 + j) * DKK + d];
        vs[i]          = g_v[((size_t)bh * SS + j0 + j) * DKK + d];
    }
    __syncthreads();

    {
        const int jj = t & 31, ug = t >> 5;
        float acc[5][4];
        #pragma unroll
        for (int a = 0; a < 5; a++) { acc[a][0]=0.f; acc[a][1]=0.f; acc[a][2]=0.f; acc[a][3]=0.f; }
        for (int d = 0; d < DKK; d++) {
            float k0v = ks[jj*65+d], k1v = ks[(jj+32)*65+d];
            float k2v = ks[(jj+64)*65+d], k3v = ks[(jj+96)*65+d];
            #pragma unroll
            for (int a = 0; a < 5; a++) {
                float qv = qs[(ug * 5 + a) * DKK + d];
                acc[a][0] += qv*k0v; acc[a][1] += qv*k1v;
                acc[a][2] += qv*k2v; acc[a][3] += qv*k3v;
            }
        }
        #pragma unroll
        for (int a = 0; a < 5; a++) {
            int u = ug * 5 + a;
            sc[u*JC+jj] = acc[a][0]; sc[u*JC+jj+32] = acc[a][1];
            sc[u*JC+jj+64] = acc[a][2]; sc[u*JC+jj+96] = acc[a][3];
        }
    }
    __syncthreads();

    {
        const int w = t >> 5, lid = t & 31;
        for (int u = w; u < UU; u += 8) {
            float a0 = sc[u*JC+lid], a1 = sc[u*JC+lid+32];
            float a2 = sc[u*JC+lid+64], a3 = sc[u*JC+lid+96];
            float mx = fmaxf(fmaxf(a0, a1), fmaxf(a2, a3));
            #pragma unroll
            for (int o = 16; o > 0; o >>= 1) mx = fmaxf(mx, __shfl_xor_sync(0xffffffffu, mx, o));
            float e0 = expf(a0-mx), e1 = expf(a1-mx), e2 = expf(a2-mx), e3 = expf(a3-mx);
            sc[u*JC+lid] = e0; sc[u*JC+lid+32] = e1; sc[u*JC+lid+64] = e2; sc[u*JC+lid+96] = e3;
            float s = e0 + e1 + e2 + e3;
            #pragma unroll
            for (int o = 16; o > 0; o >>= 1) s += __shfl_xor_sync(0xffffffffu, s, o);
            if (lid == 0) {
                g_pmax[(bh * NCH + jc) * UU + u] = mx;
                g_psum[(bh * NCH + jc) * UU + u] = s;
            }
        }
    }
    __syncthreads();

    {
        const int d2 = (t & 31) * 2, g8 = t >> 5;
        float acc[5][2];
        #pragma unroll
        for (int a = 0; a < 5; a++) { acc[a][0] = 0.f; acc[a][1] = 0.f; }
        for (int j = 0; j < JC; j++) {
            float v0 = vs[j*DKK+d2], v1 = vs[j*DKK+d2+1];
            #pragma unroll
            for (int a = 0; a < 5; a++) {
                float p = sc[(g8 * 5 + a) * JC + j];
                acc[a][0] += p * v0; acc[a][1] += p * v1;
            }
        }
        #pragma unroll
        for (int a = 0; a < 5; a++) {
            float* dst = g_po + ((size_t)(bh * NCH + jc) * UU + g8 * 5 + a) * DKK + d2;
            dst[0] = acc[a][0]; dst[1] = acc[a][1];
        }
    }
}

// ---------------- 6) merge partials + vmean finalize -> delta ------------
__global__ void attn_merge()
{
    const int bh = blockIdx.x, t = threadIdx.x;
    if (t < 64) {
        float a = 0.f;
        #pragma unroll
        for (int c = 0; c < 8; c++) a += g_vpart[(bh * 8 + c) * DKK + t];
        g_vmean[bh * DKK + t] = a * (1.0f / (float)SS);
    }
    __syncthreads();
    const int w = t >> 5, lid = t & 31;
    for (int u = w; u < UU; u += 8) {
        float M = -3.4e38f;
        #pragma unroll
        for (int c = 0; c < NCH; c++) M = fmaxf(M, g_pmax[(bh * NCH + c) * UU + u]);
        float wc[NCH], T = 0.f;
        #pragma unroll
        for (int c = 0; c < NCH; c++) {
            wc[c] = expf(g_pmax[(bh * NCH + c) * UU + u] - M);
            T += g_psum[(bh * NCH + c) * UU + u] * wc[c];
        }
        float invT = 1.0f / T;
        for (int dd = lid; dd < DKK; dd += 32) {
            float acc = 0.f;
            #pragma unroll
            for (int c = 0; c < NCH; c++)
                acc += wc[c] * g_po[((size_t)(bh * NCH + c) * UU + u) * DKK + dd];
            g_delta[(bh * UU + u) * DKK + dd] = acc * invT - g_vmean[bh * DKK + dd];
        }
    }
}

// ---------------- 7) base row --------------------------------------------
__global__ void base_kernel(const float* __restrict__ fcw)
{
    const int b = blockIdx.y;
    const int n0 = blockIdx.x * 64;
    const int t = threadIdx.x;
    const int nl = t & 63, mg = t >> 6;
    __shared__ float cv[DM];
    __shared__ float part[4][64];
    for (int i = t; i < DM; i += 256) cv[i] = g_vmean[b * DM + i];
    __syncthreads();
    float acc = 0.f;
    for (int m = mg * 256; m < mg * 256 + 256; m++)
        acc += cv[m] * fcw[(size_t)m * DM + n0 + nl];
    part[mg][nl] = acc;
    __syncthreads();
    if (t < 64)
        g_base[b * DM + n0 + t] = part[0][t] + part[1][t] + part[2][t] + part[3][t];
}

// ---------------- 8) pre = residual + base + fc_b ------------------------
__global__ void assemble_kernel(const float* __restrict__ hs, const float* __restrict__ fcb)
{
    size_t i = (size_t)blockIdx.x * 256 + threadIdx.x;
    int row = (int)(i / (DM / 4));
    int c4 = (int)(i % (DM / 4));
    int b = row >> 11;
    float4 r = ((const float4*)hs)[i];
    float4 bs = ((const float4*)g_base)[b * (DM / 4) + c4];
    float4 fb = ((const float4*)fcb)[c4];
    float4 o;
    o.x = r.x + bs.x + fb.x; o.y = r.y + bs.y + fb.y;
    o.z = r.z + bs.z + fb.z; o.w = r.w + bs.w + fb.w;
    ((float4*)g_pre)[i] = o;
}

// ---------------- 9) scatter delta-GEMM (grouped per bh) -----------------
__global__ void __launch_bounds__(256) scatter_kernel(const float* __restrict__ fcw)
{
    const int bh = blockIdx.y;
    const int n0 = blockIdx.x * 256;
    const int h = bh % HH, b = bh / HH;
    const int t = threadIdx.x;
    __shared__ float dl[UU * DKK];
    __shared__ int rows[UU];
    for (int i = t; i < UU * DKK; i += 256) dl[i] = g_delta[bh * UU * DKK + i];
    if (t < UU) rows[t] = g_top[bh * UU + t];
    __syncthreads();

    const int n = n0 + t;
    float acc[UU];
    #pragma unroll
    for (int u = 0; u < UU; u++) acc[u] = 0.f;
    const float* w = fcw + (size_t)(h * DKK) * DM + n;
    for (int d = 0; d < DKK; d++) {
        float wv = w[(size_t)d * DM];
        #pragma unroll
        for (int u = 0; u < UU; u++) acc[u] += dl[u * DKK + d] * wv;
    }
    #pragma unroll
    for (int u = 0; u < UU; u++)
        atomicAdd(&g_pre[((size_t)(b * SS + rows[u])) * DM + n], acc[u]);
}

// ---------------- 10) layernorm ------------------------------------------
__global__ void ln_kernel(const float* __restrict__ lnw, const float* __restrict__ lnb,
                          float* __restrict__ out)
{
    const int row = blockIdx.x, t = threadIdx.x;
    const float* x = g_pre + (size_t)row * DM;
    __shared__ float red[256];
    float s = 0.f;
    for (int i = t; i < DM; i += 256) s += x[i];
    red[t] = s; __syncthreads();
    for (int st = 128; st > 0; st >>= 1) { if (t < st) red[t] += red[t + st]; __syncthreads(); }
    const float mu = red[0] * (1.0f / (float)DM);
    __syncthreads();
    float v = 0.f;
    for (int i = t; i < DM; i += 256) { float dd = x[i] - mu; v += dd * dd; }
    red[t] = v; __syncthreads();
    for (int st = 128; st > 0; st >>= 1) { if (t < st) red[t] += red[t + st]; __syncthreads(); }
    const float rstd = rsqrtf(red[0] * (1.0f / (float)DM) + 1e-6f);
    for (int i = t; i < DM; i += 256)
        out[(size_t)row * DM + i] = (x[i] - mu) * rstd * lnw[i] + lnb[i];
}

// ---------------- launch --------------------------------------------------
extern "C" void kernel_launch(void* const* d_in, const int* in_sizes, int n_in,
                              void* d_out, int out_size)
{
    const float* hs  = (const float*)d_in[0];
    const float* wq  = (const float*)d_in[1];
    const float* wk  = (const float*)d_in[2];
    const float* wv  = (const float*)d_in[3];
    const float* fcw = (const float*)d_in[4];
    const float* fcb = (const float*)d_in[5];
    const float* lnw = (const float*)d_in[6];
    const float* lnb = (const float*)d_in[7];
    const int*   idx = (const int*)d_in[8];
    float* out = (float*)d_out;

    cudaFuncSetAttribute(qkv_mma, cudaFuncAttributeMaxDynamicSharedMemorySize, QSMEM);
    cudaFuncSetAttribute(attn_part, cudaFuncAttributeMaxDynamicSharedMemorySize, ATTN_SMEM);

    split2_hs<<<(int)((size_t)NR * DM / 2 / 256), 256>>>(hs);
    wtrans2<<<dim3(HDK / 32, DM / 32, 3), dim3(32, 8)>>>(wq, wk, wv);
    qkv_mma<<<dim3(HDK / 256, NR / 128, 3), 256, QSMEM>>>();
    sample_m_kernel<<<dim3(SS / 8, BH), 256>>>(idx);
    topk_kernel<<<BH, 256>>>();
    vmean_part<<<dim3(8, BH), 256>>>();
    attn_part<<<dim3(NCH, BH), 256, ATTN_SMEM>>>();
    attn_merge<<<BH, 256>>>();
    base_kernel<<<dim3(DM / 64, BB), 256>>>(fcw);
    assemble_kernel<<<(int)((size_t)NR * DM / 4 / 256), 256>>>(hs, fcb);
    scatter_kernel<<<dim3(DM / 256, BH), 256>>>(fcw);
    ln_kernel<<<NR, 256>>>(lnw, lnb, out);
}